// round 1
// baseline (speedup 1.0000x reference)
#include <cuda_runtime.h>

#define THREADS 256
#define NB 8            // batches per CTA -> 128 (b,d) columns
#define LDSD 132        // padded smem row stride (floats), 16B-aligned, bank-skewed

// shared memory layout (float offsets)
#define XS_OFF   0                      // X   : 40 x 132
#define P0_OFF   (40*LDSD)              // P0  : 64 x 132
#define P1_OFF   (P0_OFF + 64*LDSD)     // P1  : 64 x 132
#define WS_OFF   (P1_OFF + 64*LDSD)     // Wst : 40 x 132 (one h-slab of weights, transposed)
#define ACC_OFF  (WS_OFF + 40*LDSD)     // per-batch output accumulators: 8
#define SMEM_FLOATS (ACC_OFF + 8)
#define SMEM_BYTES  (SMEM_FLOATS * 4)   // 109,856 bytes

// One fused "CIN layer" GEMM: C[o,t] += sum_{h,m} W[o, h*40+m] * P[h,t] * X[m,t]
// ROWS = RPT*16 output rows starting at rowBase; each thread owns RPT x 8 outputs.
template<int H, int RPT>
__device__ __forceinline__ void layer_gemm(
    const float* __restrict__ Wg, const int ldW, const int rowBase,
    const float* __restrict__ Ps, const float* __restrict__ Xs,
    float* __restrict__ Ws,
    const int tid, const int ty, const int tcol,
    float acc[][8])
{
    constexpr int ROWS  = RPT * 16;
    constexpr int LOADS = (ROWS * 40) / THREADS;   // 20 or 10, exact

    #pragma unroll 1
    for (int h = 0; h < H; ++h) {
        __syncthreads();   // previous slab fully consumed before overwrite
        // stage W[:, h*40 .. h*40+39] into smem, transposed: Ws[m][o]
        const float* wsrc = Wg + (long)rowBase * ldW + h * 40;
        #pragma unroll
        for (int i = 0; i < LOADS; ++i) {
            int idx = tid + i * THREADS;
            int o = idx / 40;
            int m = idx - o * 40;
            Ws[m * LDSD + o] = __ldg(wsrc + (long)o * ldW + m);
        }
        __syncthreads();

        // P[h, tcol..tcol+7] is invariant over the m-loop
        float ph[8];
        {
            const float4 pa = *(const float4*)(Ps + h * LDSD + tcol);
            const float4 pb = *(const float4*)(Ps + h * LDSD + tcol + 4);
            ph[0]=pa.x; ph[1]=pa.y; ph[2]=pa.z; ph[3]=pa.w;
            ph[4]=pb.x; ph[5]=pb.y; ph[6]=pb.z; ph[7]=pb.w;
        }

        #pragma unroll 10
        for (int m = 0; m < 40; ++m) {
            const float4 xa = *(const float4*)(Xs + m * LDSD + tcol);
            const float4 xb = *(const float4*)(Xs + m * LDSD + tcol + 4);
            float z[8];
            z[0]=ph[0]*xa.x; z[1]=ph[1]*xa.y; z[2]=ph[2]*xa.z; z[3]=ph[3]*xa.w;
            z[4]=ph[4]*xb.x; z[5]=ph[5]*xb.y; z[6]=ph[6]*xb.z; z[7]=ph[7]*xb.w;

            float wv[RPT];
            #pragma unroll
            for (int q = 0; q < RPT / 4; ++q) {
                const float4 w4 = *(const float4*)(Ws + m * LDSD + ty * RPT + 4 * q);
                wv[4*q+0]=w4.x; wv[4*q+1]=w4.y; wv[4*q+2]=w4.z; wv[4*q+3]=w4.w;
            }
            #pragma unroll
            for (int r = 0; r < RPT; ++r)
                #pragma unroll
                for (int j = 0; j < 8; ++j)
                    acc[r][j] = fmaf(wv[r], z[j], acc[r][j]);
        }
    }
}

__global__ void __launch_bounds__(THREADS, 2)
cin_kernel(const float* __restrict__ x,
           const float* __restrict__ w0, const float* __restrict__ b0,
           const float* __restrict__ w1, const float* __restrict__ b1,
           const float* __restrict__ w2, const float* __restrict__ b2,
           const float* __restrict__ wl, float* __restrict__ out)
{
    extern __shared__ float sm[];
    float* Xs   = sm + XS_OFF;
    float* P0   = sm + P0_OFF;
    float* P1   = sm + P1_OFF;
    float* Ws   = sm + WS_OFF;
    float* accS = sm + ACC_OFF;

    const int tid   = threadIdx.x;
    const int bbase = blockIdx.x * NB;

    if (tid < NB) accS[tid] = 0.0f;

    // Load X tile transposed: Xs[m][t], t = lb*16 + d
    #pragma unroll
    for (int i = 0; i < (40 * 128) / THREADS; ++i) {
        int idx = tid + i * THREADS;
        int m = idx >> 7;
        int t = idx & 127;
        Xs[m * LDSD + t] = x[(bbase + (t >> 4)) * 640 + m * 16 + (t & 15)];
    }
    // (ordered by the first __syncthreads inside layer_gemm)

    const int ty   = tid >> 4;       // 0..15 -> output-row block
    const int tx   = tid & 15;       // 0..15 -> column block
    const int tcol = tx << 3;        // 8 columns, all within one batch
    const int lb   = tx >> 1;        // local batch index of this thread's columns

    float acc[8][8];

    // ---------------- Layer 0: H=40, P = X, rows 0..127 ----------------
    #pragma unroll
    for (int r = 0; r < 8; ++r)
        #pragma unroll
        for (int j = 0; j < 8; ++j) acc[r][j] = 0.0f;

    layer_gemm<40, 8>(w0, 1600, 0, Xs, Xs, Ws, tid, ty, tcol, acc);

    if (ty < 8) {
        #pragma unroll
        for (int r = 0; r < 8; ++r) {
            int o = ty * 8 + r;                     // 0..63 -> next-layer prev
            float bv = __ldg(b0 + o);
            #pragma unroll
            for (int j = 0; j < 8; ++j)
                P0[o * LDSD + tcol + j] = fmaxf(acc[r][j] + bv, 0.0f);
        }
    } else {
        float partial = 0.0f;
        #pragma unroll
        for (int r = 0; r < 8; ++r) {
            int o = ty * 8 + r;                     // 64..127 -> direct
            float bv = __ldg(b0 + o);
            float wv = __ldg(wl + (o - 64));
            float s = 0.0f;
            #pragma unroll
            for (int j = 0; j < 8; ++j) s += fmaxf(acc[r][j] + bv, 0.0f);
            partial = fmaf(wv, s, partial);
        }
        atomicAdd(&accS[lb], partial);
    }
    // (P0 writes ordered before layer1 reads by layer_gemm's leading sync)

    // ---------------- Layer 1: H=64, P = P0, rows 0..127 ----------------
    #pragma unroll
    for (int r = 0; r < 8; ++r)
        #pragma unroll
        for (int j = 0; j < 8; ++j) acc[r][j] = 0.0f;

    layer_gemm<64, 8>(w1, 2560, 0, P0, Xs, Ws, tid, ty, tcol, acc);

    if (ty < 8) {
        #pragma unroll
        for (int r = 0; r < 8; ++r) {
            int o = ty * 8 + r;
            float bv = __ldg(b1 + o);
            #pragma unroll
            for (int j = 0; j < 8; ++j)
                P1[o * LDSD + tcol + j] = fmaxf(acc[r][j] + bv, 0.0f);
        }
    } else {
        float partial = 0.0f;
        #pragma unroll
        for (int r = 0; r < 8; ++r) {
            int o = ty * 8 + r;
            float bv = __ldg(b1 + o);
            float wv = __ldg(wl + 64 + (o - 64));
            float s = 0.0f;
            #pragma unroll
            for (int j = 0; j < 8; ++j) s += fmaxf(acc[r][j] + bv, 0.0f);
            partial = fmaf(wv, s, partial);
        }
        atomicAdd(&accS[lb], partial);
    }

    // -------- Layer 2: H=64, P = P1, rows 64..127 ONLY (direct half) --------
    #pragma unroll
    for (int r = 0; r < 4; ++r)
        #pragma unroll
        for (int j = 0; j < 8; ++j) acc[r][j] = 0.0f;

    layer_gemm<64, 4>(w2, 2560, 64, P1, Xs, Ws, tid, ty, tcol, acc);

    {
        float partial = 0.0f;
        #pragma unroll
        for (int r = 0; r < 4; ++r) {
            int oc = ty * 4 + r;                    // channel-in-half 0..63
            float bv = __ldg(b2 + 64 + oc);
            float wv = __ldg(wl + 128 + oc);
            float s = 0.0f;
            #pragma unroll
            for (int j = 0; j < 8; ++j) s += fmaxf(acc[r][j] + bv, 0.0f);
            partial = fmaf(wv, s, partial);
        }
        atomicAdd(&accS[lb], partial);
    }

    __syncthreads();
    if (tid < NB) out[bbase + tid] = accS[tid];
}

extern "C" void kernel_launch(void* const* d_in, const int* in_sizes, int n_in,
                              void* d_out, int out_size)
{
    const float* x  = (const float*)d_in[0];
    const float* w0 = (const float*)d_in[1];
    const float* b0 = (const float*)d_in[2];
    const float* w1 = (const float*)d_in[3];
    const float* b1 = (const float*)d_in[4];
    const float* w2 = (const float*)d_in[5];
    const float* b2 = (const float*)d_in[6];
    const float* wl = (const float*)d_in[7];
    float* out = (float*)d_out;

    cudaFuncSetAttribute(cin_kernel,
                         cudaFuncAttributeMaxDynamicSharedMemorySize, SMEM_BYTES);
    cin_kernel<<<2048 / NB, THREADS, SMEM_BYTES>>>(x, w0, b0, w1, b1, w2, b2, wl, out);
}

// round 2
// speedup vs baseline: 1.0052x; 1.0052x over previous
#include <cuda_runtime.h>
#include <cstdint>

#define THREADS 256
#define NB 8            // batches per CTA -> 128 (b,d) columns
#define LDSD 132        // padded smem row stride (floats)

typedef unsigned long long u64;

// shared memory layout (float offsets)
#define XS_OFF   0                      // X    : 40 x 132
#define P_OFF    (40*LDSD)              // P    : 64 x 132 (layer0 out, overwritten by layer1 out)
#define WS0_OFF  (P_OFF  + 64*LDSD)     // Wbuf0: 40 x 132
#define WS1_OFF  (WS0_OFF + 40*LDSD)    // Wbuf1: 40 x 132
#define ACC_OFF  (WS1_OFF + 40*LDSD)    // per-batch output accumulators: 8
#define SMEM_FLOATS (ACC_OFF + 8)
#define SMEM_BYTES  (SMEM_FLOATS * 4)   // 97,184 bytes -> 2 CTAs/SM

// ---------------- packed f32x2 helpers ----------------
__device__ __forceinline__ u64 pack2(float a) {
    u64 r; asm("mov.b64 %0, {%1, %1};" : "=l"(r) : "f"(a)); return r;
}
__device__ __forceinline__ u64 mul2(u64 a, u64 b) {
    u64 d; asm("mul.rn.f32x2 %0, %1, %2;" : "=l"(d) : "l"(a), "l"(b)); return d;
}
__device__ __forceinline__ void fma2(u64& d, u64 a, u64 b) {
    asm("fma.rn.f32x2 %0, %1, %2, %0;" : "+l"(d) : "l"(a), "l"(b));
}
__device__ __forceinline__ void unpack2(u64 v, float& lo, float& hi) {
    asm("mov.b64 {%0, %1}, %2;" : "=f"(lo), "=f"(hi) : "l"(v));
}

// stage W[:, h*40 .. h*40+39] (ROWS rows) into smem transposed: Wbuf[m][o]
template<int ROWS>
__device__ __forceinline__ void stage_w(const float* __restrict__ wsrc, const int ldW,
                                        float* __restrict__ Wbuf, const int tid)
{
    constexpr int LOADS = (ROWS * 40) / THREADS;   // 20 (ROWS=128) or 10 (ROWS=64)
    #pragma unroll
    for (int i = 0; i < LOADS; ++i) {
        int idx = tid + i * THREADS;
        int o = idx / 40;
        int m = idx - o * 40;
        Wbuf[m * LDSD + o] = __ldg(wsrc + (long)o * ldW + m);
    }
}

// One fused CIN-layer GEMM: C[o,t] += sum_{h,m} W[o,h*40+m] * P[h,t] * X[m,t]
// ROWS = RPT*16 output rows starting at rowBase; each thread owns RPT rows x 8 cols
// (held as RPT x 4 packed f32x2 accumulators).
template<int H, int RPT>
__device__ __forceinline__ void layer_gemm(
    const float* __restrict__ Wg, const int ldW, const int rowBase,
    const float* __restrict__ Ps, const float* __restrict__ Xs,
    float* __restrict__ Ws0, float* __restrict__ Ws1,
    const int tid, const int ty, const int tcol,
    u64 acc[][4])
{
    constexpr int ROWS = RPT * 16;
    const float* __restrict__ wbase = Wg + (long)rowBase * ldW;

    // prologue: stage h=0 into buffer 0
    stage_w<ROWS>(wbase, ldW, Ws0, tid);
    __syncthreads();

    #pragma unroll 1
    for (int h = 0; h < H; ++h) {
        // prefetch next slab into the other buffer (overlaps with compute below)
        if (h + 1 < H)
            stage_w<ROWS>(wbase + (h + 1) * 40, ldW, ((h + 1) & 1) ? Ws1 : Ws0, tid);

        const float* __restrict__ Wc = (h & 1) ? Ws1 : Ws0;

        // P[h, tcol..tcol+7] packed as 4 f32x2 pairs, invariant over the m-loop
        u64 ph[4];
        {
            const ulonglong2 pa = *(const ulonglong2*)(Ps + h * LDSD + tcol);
            const ulonglong2 pb = *(const ulonglong2*)(Ps + h * LDSD + tcol + 4);
            ph[0] = pa.x; ph[1] = pa.y; ph[2] = pb.x; ph[3] = pb.y;
        }

        #pragma unroll 8
        for (int m = 0; m < 40; ++m) {
            const ulonglong2 xa = *(const ulonglong2*)(Xs + m * LDSD + tcol);
            const ulonglong2 xb = *(const ulonglong2*)(Xs + m * LDSD + tcol + 4);
            u64 z[4];
            z[0] = mul2(ph[0], xa.x);
            z[1] = mul2(ph[1], xa.y);
            z[2] = mul2(ph[2], xb.x);
            z[3] = mul2(ph[3], xb.y);

            #pragma unroll
            for (int q = 0; q < RPT / 4; ++q) {
                const float4 w4 = *(const float4*)(Wc + m * LDSD + ty * RPT + 4 * q);
                u64 wp0 = pack2(w4.x), wp1 = pack2(w4.y), wp2 = pack2(w4.z), wp3 = pack2(w4.w);
                #pragma unroll
                for (int k = 0; k < 4; ++k) fma2(acc[4*q + 0][k], wp0, z[k]);
                #pragma unroll
                for (int k = 0; k < 4; ++k) fma2(acc[4*q + 1][k], wp1, z[k]);
                #pragma unroll
                for (int k = 0; k < 4; ++k) fma2(acc[4*q + 2][k], wp2, z[k]);
                #pragma unroll
                for (int k = 0; k < 4; ++k) fma2(acc[4*q + 3][k], wp3, z[k]);
            }
        }
        __syncthreads();   // staged h+1 visible; all reads of Wc done before its reuse
    }
}

__global__ void __launch_bounds__(THREADS, 2)
cin_kernel(const float* __restrict__ x,
           const float* __restrict__ w0, const float* __restrict__ b0,
           const float* __restrict__ w1, const float* __restrict__ b1,
           const float* __restrict__ w2, const float* __restrict__ b2,
           const float* __restrict__ wl, float* __restrict__ out)
{
    extern __shared__ float sm[];
    float* Xs   = sm + XS_OFF;
    float* Pbuf = sm + P_OFF;
    float* Ws0  = sm + WS0_OFF;
    float* Ws1  = sm + WS1_OFF;
    float* accS = sm + ACC_OFF;

    const int tid   = threadIdx.x;
    const int bbase = blockIdx.x * NB;

    if (tid < NB) accS[tid] = 0.0f;

    // Load X tile transposed: Xs[m][t], t = lb*16 + d
    #pragma unroll
    for (int i = 0; i < (40 * 128) / THREADS; ++i) {
        int idx = tid + i * THREADS;
        int m = idx >> 7;
        int t = idx & 127;
        Xs[m * LDSD + t] = x[(bbase + (t >> 4)) * 640 + m * 16 + (t & 15)];
    }
    // ordered before first use by the sync inside layer_gemm's prologue

    const int ty   = tid >> 4;       // 0..15 -> output-row block
    const int tx   = tid & 15;       // 0..15 -> column block
    const int tcol = tx << 3;        // 8 columns, within one batch
    const int lb   = tx >> 1;        // local batch index of this thread's columns

    u64 acc[8][4];

    // ---------------- Layer 0: H=40, P = X, rows 0..127 ----------------
    #pragma unroll
    for (int r = 0; r < 8; ++r)
        #pragma unroll
        for (int k = 0; k < 4; ++k) acc[r][k] = 0ull;

    layer_gemm<40, 8>(w0, 1600, 0, Xs, Xs, Ws0, Ws1, tid, ty, tcol, acc);

    if (ty < 8) {
        #pragma unroll
        for (int r = 0; r < 8; ++r) {
            int o = ty * 8 + r;                     // 0..63 -> next-layer prev
            float bv = __ldg(b0 + o);
            #pragma unroll
            for (int k = 0; k < 4; ++k) {
                float lo, hi; unpack2(acc[r][k], lo, hi);
                Pbuf[o * LDSD + tcol + 2*k    ] = fmaxf(lo + bv, 0.0f);
                Pbuf[o * LDSD + tcol + 2*k + 1] = fmaxf(hi + bv, 0.0f);
            }
        }
    } else {
        float partial = 0.0f;
        #pragma unroll
        for (int r = 0; r < 8; ++r) {
            int o = ty * 8 + r;                     // 64..127 -> direct
            float bv = __ldg(b0 + o);
            float wv = __ldg(wl + (o - 64));
            float s = 0.0f;
            #pragma unroll
            for (int k = 0; k < 4; ++k) {
                float lo, hi; unpack2(acc[r][k], lo, hi);
                s += fmaxf(lo + bv, 0.0f) + fmaxf(hi + bv, 0.0f);
            }
            partial = fmaf(wv, s, partial);
        }
        atomicAdd(&accS[lb], partial);
    }
    // Pbuf writes ordered before layer-1 compute by layer_gemm's prologue sync

    // ---------------- Layer 1: H=64, P = Pbuf, rows 0..127 ----------------
    #pragma unroll
    for (int r = 0; r < 8; ++r)
        #pragma unroll
        for (int k = 0; k < 4; ++k) acc[r][k] = 0ull;

    layer_gemm<64, 8>(w1, 2560, 0, Pbuf, Xs, Ws0, Ws1, tid, ty, tcol, acc);

    if (ty < 8) {
        // overwrite Pbuf in place: all reads of old P finished (final sync of layer_gemm)
        #pragma unroll
        for (int r = 0; r < 8; ++r) {
            int o = ty * 8 + r;
            float bv = __ldg(b1 + o);
            #pragma unroll
            for (int k = 0; k < 4; ++k) {
                float lo, hi; unpack2(acc[r][k], lo, hi);
                Pbuf[o * LDSD + tcol + 2*k    ] = fmaxf(lo + bv, 0.0f);
                Pbuf[o * LDSD + tcol + 2*k + 1] = fmaxf(hi + bv, 0.0f);
            }
        }
    } else {
        float partial = 0.0f;
        #pragma unroll
        for (int r = 0; r < 8; ++r) {
            int o = ty * 8 + r;
            float bv = __ldg(b1 + o);
            float wv = __ldg(wl + 64 + (o - 64));
            float s = 0.0f;
            #pragma unroll
            for (int k = 0; k < 4; ++k) {
                float lo, hi; unpack2(acc[r][k], lo, hi);
                s += fmaxf(lo + bv, 0.0f) + fmaxf(hi + bv, 0.0f);
            }
            partial = fmaf(wv, s, partial);
        }
        atomicAdd(&accS[lb], partial);
    }

    // -------- Layer 2: H=64, P = Pbuf, rows 64..127 ONLY (direct half) --------
    #pragma unroll
    for (int r = 0; r < 4; ++r)
        #pragma unroll
        for (int k = 0; k < 4; ++k) acc[r][k] = 0ull;

    layer_gemm<64, 4>(w2, 2560, 64, Pbuf, Xs, Ws0, Ws1, tid, ty, tcol, acc);

    {
        float partial = 0.0f;
        #pragma unroll
        for (int r = 0; r < 4; ++r) {
            int oc = ty * 4 + r;                    // channel-in-half 0..63
            float bv = __ldg(b2 + 64 + oc);
            float wv = __ldg(wl + 128 + oc);
            float s = 0.0f;
            #pragma unroll
            for (int k = 0; k < 4; ++k) {
                float lo, hi; unpack2(acc[r][k], lo, hi);
                s += fmaxf(lo + bv, 0.0f) + fmaxf(hi + bv, 0.0f);
            }
            partial = fmaf(wv, s, partial);
        }
        atomicAdd(&accS[lb], partial);
    }

    __syncthreads();
    if (tid < NB) out[bbase + tid] = accS[tid];
}

extern "C" void kernel_launch(void* const* d_in, const int* in_sizes, int n_in,
                              void* d_out, int out_size)
{
    const float* x  = (const float*)d_in[0];
    const float* w0 = (const float*)d_in[1];
    const float* b0 = (const float*)d_in[2];
    const float* w1 = (const float*)d_in[3];
    const float* b1 = (const float*)d_in[4];
    const float* w2 = (const float*)d_in[5];
    const float* b2 = (const float*)d_in[6];
    const float* wl = (const float*)d_in[7];
    float* out = (float*)d_out;

    cudaFuncSetAttribute(cin_kernel,
                         cudaFuncAttributeMaxDynamicSharedMemorySize, SMEM_BYTES);
    cin_kernel<<<2048 / NB, THREADS, SMEM_BYTES>>>(x, w0, b0, w1, b1, w2, b2, wl, out);
}

// round 3
// speedup vs baseline: 1.0078x; 1.0026x over previous
#include <cuda_runtime.h>
#include <cstdint>

#define THREADS 256
#define NB 8            // batches per CTA -> 128 (b,d) columns
#define LDSD 132        // padded smem row stride (floats)

typedef unsigned long long u64;

// shared memory layout (float offsets)
#define XS_OFF   0                      // X    : 40 x 132
#define P_OFF    (40*LDSD)              // P    : 64 x 132 (layer0 out, overwritten by layer1 out)
#define WS0_OFF  (P_OFF  + 64*LDSD)     // Wbuf0: 40 x 132
#define WS1_OFF  (WS0_OFF + 40*LDSD)    // Wbuf1: 40 x 132
#define ACC_OFF  (WS1_OFF + 40*LDSD)    // per-batch output accumulators: 8
#define SMEM_FLOATS (ACC_OFF + 8)
#define SMEM_BYTES  (SMEM_FLOATS * 4)   // 97,184 bytes -> 2 CTAs/SM

// ---------------- packed f32x2 helpers ----------------
__device__ __forceinline__ u64 pack2(float a) {
    u64 r; asm("mov.b64 %0, {%1, %1};" : "=l"(r) : "f"(a)); return r;
}
__device__ __forceinline__ u64 mul2(u64 a, u64 b) {
    u64 d; asm("mul.rn.f32x2 %0, %1, %2;" : "=l"(d) : "l"(a), "l"(b)); return d;
}
__device__ __forceinline__ void fma2(u64& d, u64 a, u64 b) {
    asm("fma.rn.f32x2 %0, %1, %2, %0;" : "+l"(d) : "l"(a), "l"(b));
}
__device__ __forceinline__ void unpack2(u64 v, float& lo, float& hi) {
    asm("mov.b64 {%0, %1}, %2;" : "=f"(lo), "=f"(hi) : "l"(v));
}

// stage W[:, h*40 .. h*40+39] (ROWS rows) into smem transposed: Wbuf[m][o]
template<int ROWS>
__device__ __forceinline__ void stage_w(const float* __restrict__ wsrc, const int ldW,
                                        float* __restrict__ Wbuf, const int tid)
{
    constexpr int LOADS = (ROWS * 40) / THREADS;   // 20 (ROWS=128) or 10 (ROWS=64)
    #pragma unroll
    for (int i = 0; i < LOADS; ++i) {
        int idx = tid + i * THREADS;
        int o = idx / 40;
        int m = idx - o * 40;
        Wbuf[m * LDSD + o] = __ldg(wsrc + (long)o * ldW + m);
    }
}

// One fused CIN-layer GEMM: C[o,t] += sum_{h,m} W[o,h*40+m] * P[h,t] * X[m,t]
// ROWS = RPT*16 output rows starting at rowBase; each thread owns RPT rows x 8 cols
// (held as RPT x 4 packed f32x2 accumulators).
template<int H, int RPT>
__device__ __forceinline__ void layer_gemm(
    const float* __restrict__ Wg, const int ldW, const int rowBase,
    const float* __restrict__ Ps, const float* __restrict__ Xs,
    float* __restrict__ Ws0, float* __restrict__ Ws1,
    const int tid, const int ty, const int tcol,
    u64 acc[][4])
{
    constexpr int ROWS = RPT * 16;
    const float* __restrict__ wbase = Wg + (long)rowBase * ldW;

    // prologue: stage h=0 into buffer 0
    stage_w<ROWS>(wbase, ldW, Ws0, tid);
    __syncthreads();

    #pragma unroll 1
    for (int h = 0; h < H; ++h) {
        // prefetch next slab into the other buffer (overlaps with compute below)
        if (h + 1 < H)
            stage_w<ROWS>(wbase + (h + 1) * 40, ldW, ((h + 1) & 1) ? Ws1 : Ws0, tid);

        const float* __restrict__ Wc = (h & 1) ? Ws1 : Ws0;

        // P[h, tcol..tcol+7] packed as 4 f32x2 pairs, invariant over the m-loop
        u64 ph[4];
        {
            const ulonglong2 pa = *(const ulonglong2*)(Ps + h * LDSD + tcol);
            const ulonglong2 pb = *(const ulonglong2*)(Ps + h * LDSD + tcol + 4);
            ph[0] = pa.x; ph[1] = pa.y; ph[2] = pb.x; ph[3] = pb.y;
        }

        #pragma unroll 8
        for (int m = 0; m < 40; ++m) {
            const ulonglong2 xa = *(const ulonglong2*)(Xs + m * LDSD + tcol);
            const ulonglong2 xb = *(const ulonglong2*)(Xs + m * LDSD + tcol + 4);
            u64 z[4];
            z[0] = mul2(ph[0], xa.x);
            z[1] = mul2(ph[1], xa.y);
            z[2] = mul2(ph[2], xb.x);
            z[3] = mul2(ph[3], xb.y);

            #pragma unroll
            for (int q = 0; q < RPT / 4; ++q) {
                const float4 w4 = *(const float4*)(Wc + m * LDSD + ty * RPT + 4 * q);
                u64 wp0 = pack2(w4.x), wp1 = pack2(w4.y), wp2 = pack2(w4.z), wp3 = pack2(w4.w);
                #pragma unroll
                for (int k = 0; k < 4; ++k) fma2(acc[4*q + 0][k], wp0, z[k]);
                #pragma unroll
                for (int k = 0; k < 4; ++k) fma2(acc[4*q + 1][k], wp1, z[k]);
                #pragma unroll
                for (int k = 0; k < 4; ++k) fma2(acc[4*q + 2][k], wp2, z[k]);
                #pragma unroll
                for (int k = 0; k < 4; ++k) fma2(acc[4*q + 3][k], wp3, z[k]);
            }
        }
        __syncthreads();   // staged h+1 visible; all reads of Wc done before its reuse
    }
}

__global__ void __launch_bounds__(THREADS, 2)
cin_kernel(const float* __restrict__ x,
           const float* __restrict__ w0, const float* __restrict__ b0,
           const float* __restrict__ w1, const float* __restrict__ b1,
           const float* __restrict__ w2, const float* __restrict__ b2,
           const float* __restrict__ wl, float* __restrict__ out)
{
    extern __shared__ float sm[];
    float* Xs   = sm + XS_OFF;
    float* Pbuf = sm + P_OFF;
    float* Ws0  = sm + WS0_OFF;
    float* Ws1  = sm + WS1_OFF;
    float* accS = sm + ACC_OFF;

    const int tid   = threadIdx.x;
    const int bbase = blockIdx.x * NB;

    if (tid < NB) accS[tid] = 0.0f;

    // Load X tile transposed: Xs[m][t], t = lb*16 + d
    #pragma unroll
    for (int i = 0; i < (40 * 128) / THREADS; ++i) {
        int idx = tid + i * THREADS;
        int m = idx >> 7;
        int t = idx & 127;
        Xs[m * LDSD + t] = x[(bbase + (t >> 4)) * 640 + m * 16 + (t & 15)];
    }
    // ordered before first use by the sync inside layer_gemm's prologue

    const int ty   = tid >> 4;       // 0..15 -> output-row block
    const int tx   = tid & 15;       // 0..15 -> column block
    const int tcol = tx << 3;        // 8 columns, within one batch
    const int lb   = tx >> 1;        // local batch index of this thread's columns

    u64 acc[8][4];

    // ---------------- Layer 0: H=40, P = X, rows 0..127 ----------------
    #pragma unroll
    for (int r = 0; r < 8; ++r)
        #pragma unroll
        for (int k = 0; k < 4; ++k) acc[r][k] = 0ull;

    layer_gemm<40, 8>(w0, 1600, 0, Xs, Xs, Ws0, Ws1, tid, ty, tcol, acc);

    if (ty < 8) {
        #pragma unroll
        for (int r = 0; r < 8; ++r) {
            int o = ty * 8 + r;                     // 0..63 -> next-layer prev
            float bv = __ldg(b0 + o);
            #pragma unroll
            for (int k = 0; k < 4; ++k) {
                float lo, hi; unpack2(acc[r][k], lo, hi);
                Pbuf[o * LDSD + tcol + 2*k    ] = fmaxf(lo + bv, 0.0f);
                Pbuf[o * LDSD + tcol + 2*k + 1] = fmaxf(hi + bv, 0.0f);
            }
        }
    } else {
        float partial = 0.0f;
        #pragma unroll
        for (int r = 0; r < 8; ++r) {
            int o = ty * 8 + r;                     // 64..127 -> direct
            float bv = __ldg(b0 + o);
            float wv = __ldg(wl + (o - 64));
            float s = 0.0f;
            #pragma unroll
            for (int k = 0; k < 4; ++k) {
                float lo, hi; unpack2(acc[r][k], lo, hi);
                s += fmaxf(lo + bv, 0.0f) + fmaxf(hi + bv, 0.0f);
            }
            partial = fmaf(wv, s, partial);
        }
        atomicAdd(&accS[lb], partial);
    }
    // Pbuf writes ordered before layer-1 compute by layer_gemm's prologue sync

    // ---------------- Layer 1: H=64, P = Pbuf, rows 0..127 ----------------
    #pragma unroll
    for (int r = 0; r < 8; ++r)
        #pragma unroll
        for (int k = 0; k < 4; ++k) acc[r][k] = 0ull;

    layer_gemm<64, 8>(w1, 2560, 0, Pbuf, Xs, Ws0, Ws1, tid, ty, tcol, acc);

    if (ty < 8) {
        // overwrite Pbuf in place: all reads of old P finished (final sync of layer_gemm)
        #pragma unroll
        for (int r = 0; r < 8; ++r) {
            int o = ty * 8 + r;
            float bv = __ldg(b1 + o);
            #pragma unroll
            for (int k = 0; k < 4; ++k) {
                float lo, hi; unpack2(acc[r][k], lo, hi);
                Pbuf[o * LDSD + tcol + 2*k    ] = fmaxf(lo + bv, 0.0f);
                Pbuf[o * LDSD + tcol + 2*k + 1] = fmaxf(hi + bv, 0.0f);
            }
        }
    } else {
        float partial = 0.0f;
        #pragma unroll
        for (int r = 0; r < 8; ++r) {
            int o = ty * 8 + r;
            float bv = __ldg(b1 + o);
            float wv = __ldg(wl + 64 + (o - 64));
            float s = 0.0f;
            #pragma unroll
            for (int k = 0; k < 4; ++k) {
                float lo, hi; unpack2(acc[r][k], lo, hi);
                s += fmaxf(lo + bv, 0.0f) + fmaxf(hi + bv, 0.0f);
            }
            partial = fmaf(wv, s, partial);
        }
        atomicAdd(&accS[lb], partial);
    }

    // -------- Layer 2: H=64, P = Pbuf, rows 64..127 ONLY (direct half) --------
    #pragma unroll
    for (int r = 0; r < 4; ++r)
        #pragma unroll
        for (int k = 0; k < 4; ++k) acc[r][k] = 0ull;

    layer_gemm<64, 4>(w2, 2560, 64, Pbuf, Xs, Ws0, Ws1, tid, ty, tcol, acc);

    {
        float partial = 0.0f;
        #pragma unroll
        for (int r = 0; r < 4; ++r) {
            int oc = ty * 4 + r;                    // channel-in-half 0..63
            float bv = __ldg(b2 + 64 + oc);
            float wv = __ldg(wl + 128 + oc);
            float s = 0.0f;
            #pragma unroll
            for (int k = 0; k < 4; ++k) {
                float lo, hi; unpack2(acc[r][k], lo, hi);
                s += fmaxf(lo + bv, 0.0f) + fmaxf(hi + bv, 0.0f);
            }
            partial = fmaf(wv, s, partial);
        }
        atomicAdd(&accS[lb], partial);
    }

    __syncthreads();
    if (tid < NB) out[bbase + tid] = accS[tid];
}

extern "C" void kernel_launch(void* const* d_in, const int* in_sizes, int n_in,
                              void* d_out, int out_size)
{
    const float* x  = (const float*)d_in[0];
    const float* w0 = (const float*)d_in[1];
    const float* b0 = (const float*)d_in[2];
    const float* w1 = (const float*)d_in[3];
    const float* b1 = (const float*)d_in[4];
    const float* w2 = (const float*)d_in[5];
    const float* b2 = (const float*)d_in[6];
    const float* wl = (const float*)d_in[7];
    float* out = (float*)d_out;

    cudaFuncSetAttribute(cin_kernel,
                         cudaFuncAttributeMaxDynamicSharedMemorySize, SMEM_BYTES);
    cin_kernel<<<2048 / NB, THREADS, SMEM_BYTES>>>(x, w0, b0, w1, b1, w2, b2, wl, out);
}

// round 4
// speedup vs baseline: 1.0082x; 1.0003x over previous
#include <cuda_runtime.h>
#include <cstdint>

#define THREADS 256
#define NB 8            // batches per CTA -> 128 (b,d) columns
#define LDSD 132        // padded smem row stride (floats)

typedef unsigned long long u64;

// shared memory layout (float offsets)
#define XS_OFF   0                      // X    : 40 x 132
#define P_OFF    (40*LDSD)              // P    : 64 x 132 (layer0 out, overwritten by layer1 out)
#define WS0_OFF  (P_OFF  + 64*LDSD)     // Wbuf0: 40 x 132
#define WS1_OFF  (WS0_OFF + 40*LDSD)    // Wbuf1: 40 x 132
#define ACC_OFF  (WS1_OFF + 40*LDSD)    // per-batch output accumulators: 8
#define SMEM_FLOATS (ACC_OFF + 8)
#define SMEM_BYTES  (SMEM_FLOATS * 4)   // 97,184 bytes -> 2 CTAs/SM

// ---------------- packed f32x2 helpers ----------------
__device__ __forceinline__ u64 pack2(float a) {
    u64 r; asm("mov.b64 %0, {%1, %1};" : "=l"(r) : "f"(a)); return r;
}
__device__ __forceinline__ u64 mul2(u64 a, u64 b) {
    u64 d; asm("mul.rn.f32x2 %0, %1, %2;" : "=l"(d) : "l"(a), "l"(b)); return d;
}
__device__ __forceinline__ void fma2(u64& d, u64 a, u64 b) {
    asm("fma.rn.f32x2 %0, %1, %2, %0;" : "+l"(d) : "l"(a), "l"(b));
}
__device__ __forceinline__ void unpack2(u64 v, float& lo, float& hi) {
    asm("mov.b64 {%0, %1}, %2;" : "=f"(lo), "=f"(hi) : "l"(v));
}

// stage W[:, h*40 .. h*40+39] (ROWS rows) into smem transposed: Wbuf[m][o]
template<int ROWS>
__device__ __forceinline__ void stage_w(const float* __restrict__ wsrc, const int ldW,
                                        float* __restrict__ Wbuf, const int tid)
{
    constexpr int LOADS = (ROWS * 40) / THREADS;   // 20 (ROWS=128) or 10 (ROWS=64)
    #pragma unroll
    for (int i = 0; i < LOADS; ++i) {
        int idx = tid + i * THREADS;
        int o = idx / 40;
        int m = idx - o * 40;
        Wbuf[m * LDSD + o] = __ldg(wsrc + (long)o * ldW + m);
    }
}

// One fused CIN-layer GEMM: C[o,t] += sum_{h,m} W[o,h*40+m] * P[h,t] * X[m,t]
// ROWS = RPT*16 output rows starting at rowBase; each thread owns RPT rows x 8 cols
// (held as RPT x 4 packed f32x2 accumulators).
template<int H, int RPT>
__device__ __forceinline__ void layer_gemm(
    const float* __restrict__ Wg, const int ldW, const int rowBase,
    const float* __restrict__ Ps, const float* __restrict__ Xs,
    float* __restrict__ Ws0, float* __restrict__ Ws1,
    const int tid, const int ty, const int tcol,
    u64 acc[][4])
{
    constexpr int ROWS = RPT * 16;
    const float* __restrict__ wbase = Wg + (long)rowBase * ldW;

    // prologue: stage h=0 into buffer 0
    stage_w<ROWS>(wbase, ldW, Ws0, tid);
    __syncthreads();

    #pragma unroll 1
    for (int h = 0; h < H; ++h) {
        // prefetch next slab into the other buffer (overlaps with compute below)
        if (h + 1 < H)
            stage_w<ROWS>(wbase + (h + 1) * 40, ldW, ((h + 1) & 1) ? Ws1 : Ws0, tid);

        const float* __restrict__ Wc = (h & 1) ? Ws1 : Ws0;

        // P[h, tcol..tcol+7] packed as 4 f32x2 pairs, invariant over the m-loop
        u64 ph[4];
        {
            const ulonglong2 pa = *(const ulonglong2*)(Ps + h * LDSD + tcol);
            const ulonglong2 pb = *(const ulonglong2*)(Ps + h * LDSD + tcol + 4);
            ph[0] = pa.x; ph[1] = pa.y; ph[2] = pb.x; ph[3] = pb.y;
        }

        #pragma unroll 8
        for (int m = 0; m < 40; ++m) {
            const ulonglong2 xa = *(const ulonglong2*)(Xs + m * LDSD + tcol);
            const ulonglong2 xb = *(const ulonglong2*)(Xs + m * LDSD + tcol + 4);
            u64 z[4];
            z[0] = mul2(ph[0], xa.x);
            z[1] = mul2(ph[1], xa.y);
            z[2] = mul2(ph[2], xb.x);
            z[3] = mul2(ph[3], xb.y);

            #pragma unroll
            for (int q = 0; q < RPT / 4; ++q) {
                const float4 w4 = *(const float4*)(Wc + m * LDSD + ty * RPT + 4 * q);
                u64 wp0 = pack2(w4.x), wp1 = pack2(w4.y), wp2 = pack2(w4.z), wp3 = pack2(w4.w);
                #pragma unroll
                for (int k = 0; k < 4; ++k) fma2(acc[4*q + 0][k], wp0, z[k]);
                #pragma unroll
                for (int k = 0; k < 4; ++k) fma2(acc[4*q + 1][k], wp1, z[k]);
                #pragma unroll
                for (int k = 0; k < 4; ++k) fma2(acc[4*q + 2][k], wp2, z[k]);
                #pragma unroll
                for (int k = 0; k < 4; ++k) fma2(acc[4*q + 3][k], wp3, z[k]);
            }
        }
        __syncthreads();   // staged h+1 visible; all reads of Wc done before its reuse
    }
}

__global__ void __launch_bounds__(THREADS, 2)
cin_kernel(const float* __restrict__ x,
           const float* __restrict__ w0, const float* __restrict__ b0,
           const float* __restrict__ w1, const float* __restrict__ b1,
           const float* __restrict__ w2, const float* __restrict__ b2,
           const float* __restrict__ wl, float* __restrict__ out)
{
    extern __shared__ float sm[];
    float* Xs   = sm + XS_OFF;
    float* Pbuf = sm + P_OFF;
    float* Ws0  = sm + WS0_OFF;
    float* Ws1  = sm + WS1_OFF;
    float* accS = sm + ACC_OFF;

    const int tid   = threadIdx.x;
    const int bbase = blockIdx.x * NB;

    if (tid < NB) accS[tid] = 0.0f;

    // Load X tile transposed: Xs[m][t], t = lb*16 + d
    #pragma unroll
    for (int i = 0; i < (40 * 128) / THREADS; ++i) {
        int idx = tid + i * THREADS;
        int m = idx >> 7;
        int t = idx & 127;
        Xs[m * LDSD + t] = x[(bbase + (t >> 4)) * 640 + m * 16 + (t & 15)];
    }
    // ordered before first use by the sync inside layer_gemm's prologue

    const int ty   = tid >> 4;       // 0..15 -> output-row block
    const int tx   = tid & 15;       // 0..15 -> column block
    const int tcol = tx << 3;        // 8 columns, within one batch
    const int lb   = tx >> 1;        // local batch index of this thread's columns

    u64 acc[8][4];

    // ---------------- Layer 0: H=40, P = X, rows 0..127 ----------------
    #pragma unroll
    for (int r = 0; r < 8; ++r)
        #pragma unroll
        for (int k = 0; k < 4; ++k) acc[r][k] = 0ull;

    layer_gemm<40, 8>(w0, 1600, 0, Xs, Xs, Ws0, Ws1, tid, ty, tcol, acc);

    if (ty < 8) {
        #pragma unroll
        for (int r = 0; r < 8; ++r) {
            int o = ty * 8 + r;                     // 0..63 -> next-layer prev
            float bv = __ldg(b0 + o);
            #pragma unroll
            for (int k = 0; k < 4; ++k) {
                float lo, hi; unpack2(acc[r][k], lo, hi);
                Pbuf[o * LDSD + tcol + 2*k    ] = fmaxf(lo + bv, 0.0f);
                Pbuf[o * LDSD + tcol + 2*k + 1] = fmaxf(hi + bv, 0.0f);
            }
        }
    } else {
        float partial = 0.0f;
        #pragma unroll
        for (int r = 0; r < 8; ++r) {
            int o = ty * 8 + r;                     // 64..127 -> direct
            float bv = __ldg(b0 + o);
            float wv = __ldg(wl + (o - 64));
            float s = 0.0f;
            #pragma unroll
            for (int k = 0; k < 4; ++k) {
                float lo, hi; unpack2(acc[r][k], lo, hi);
                s += fmaxf(lo + bv, 0.0f) + fmaxf(hi + bv, 0.0f);
            }
            partial = fmaf(wv, s, partial);
        }
        atomicAdd(&accS[lb], partial);
    }
    // Pbuf writes ordered before layer-1 compute by layer_gemm's prologue sync

    // ---------------- Layer 1: H=64, P = Pbuf, rows 0..127 ----------------
    #pragma unroll
    for (int r = 0; r < 8; ++r)
        #pragma unroll
        for (int k = 0; k < 4; ++k) acc[r][k] = 0ull;

    layer_gemm<64, 8>(w1, 2560, 0, Pbuf, Xs, Ws0, Ws1, tid, ty, tcol, acc);

    if (ty < 8) {
        // overwrite Pbuf in place: all reads of old P finished (final sync of layer_gemm)
        #pragma unroll
        for (int r = 0; r < 8; ++r) {
            int o = ty * 8 + r;
            float bv = __ldg(b1 + o);
            #pragma unroll
            for (int k = 0; k < 4; ++k) {
                float lo, hi; unpack2(acc[r][k], lo, hi);
                Pbuf[o * LDSD + tcol + 2*k    ] = fmaxf(lo + bv, 0.0f);
                Pbuf[o * LDSD + tcol + 2*k + 1] = fmaxf(hi + bv, 0.0f);
            }
        }
    } else {
        float partial = 0.0f;
        #pragma unroll
        for (int r = 0; r < 8; ++r) {
            int o = ty * 8 + r;
            float bv = __ldg(b1 + o);
            float wv = __ldg(wl + 64 + (o - 64));
            float s = 0.0f;
            #pragma unroll
            for (int k = 0; k < 4; ++k) {
                float lo, hi; unpack2(acc[r][k], lo, hi);
                s += fmaxf(lo + bv, 0.0f) + fmaxf(hi + bv, 0.0f);
            }
            partial = fmaf(wv, s, partial);
        }
        atomicAdd(&accS[lb], partial);
    }

    // -------- Layer 2: H=64, P = Pbuf, rows 64..127 ONLY (direct half) --------
    #pragma unroll
    for (int r = 0; r < 4; ++r)
        #pragma unroll
        for (int k = 0; k < 4; ++k) acc[r][k] = 0ull;

    layer_gemm<64, 4>(w2, 2560, 64, Pbuf, Xs, Ws0, Ws1, tid, ty, tcol, acc);

    {
        float partial = 0.0f;
        #pragma unroll
        for (int r = 0; r < 4; ++r) {
            int oc = ty * 4 + r;                    // channel-in-half 0..63
            float bv = __ldg(b2 + 64 + oc);
            float wv = __ldg(wl + 128 + oc);
            float s = 0.0f;
            #pragma unroll
            for (int k = 0; k < 4; ++k) {
                float lo, hi; unpack2(acc[r][k], lo, hi);
                s += fmaxf(lo + bv, 0.0f) + fmaxf(hi + bv, 0.0f);
            }
            partial = fmaf(wv, s, partial);
        }
        atomicAdd(&accS[lb], partial);
    }

    __syncthreads();
    if (tid < NB) out[bbase + tid] = accS[tid];
}

extern "C" void kernel_launch(void* const* d_in, const int* in_sizes, int n_in,
                              void* d_out, int out_size)
{
    const float* x  = (const float*)d_in[0];
    const float* w0 = (const float*)d_in[1];
    const float* b0 = (const float*)d_in[2];
    const float* w1 = (const float*)d_in[3];
    const float* b1 = (const float*)d_in[4];
    const float* w2 = (const float*)d_in[5];
    const float* b2 = (const float*)d_in[6];
    const float* wl = (const float*)d_in[7];
    float* out = (float*)d_out;

    cudaFuncSetAttribute(cin_kernel,
                         cudaFuncAttributeMaxDynamicSharedMemorySize, SMEM_BYTES);
    cin_kernel<<<2048 / NB, THREADS, SMEM_BYTES>>>(x, w0, b0, w1, b1, w2, b2, wl, out);
}

// round 6
// speedup vs baseline: 2.6575x; 2.6360x over previous
#include <cuda_runtime.h>
#include <cuda_bf16.h>
#include <cstdint>

#define THREADS 512
#define LDP 264                      // padded smem row stride (floats): conflict-free

// ---------------- smem byte layout ----------------
#define SM_XS 0                              // X : 40 x 264 f32 = 42240
#define SM_PS (40*LDP*4)                     // P : 64 x 264 f32 = 67584
#define SM_W0 (SM_PS + 64*LDP*4)             // W chunk buf0 (8KB)
#define SM_W1 (SM_W0 + 8192)                 // W chunk buf1 (8KB)
#define SMEM_BYTES (SM_W1 + 8192)            // 126,208 bytes

// ---------------- prepped-W global scratch ----------------
// Per k16-chunk: NT n-tiles x {hi,lo} x 64 b32 words in exact B-fragment
// register order (lane-major, b0/b1 adjacent per lane -> one LDS.b64).
#define NT0 16
#define NT1 16
#define NT2 8
#define CH0 100
#define CH1 160
#define CH2 160
#define CHB0 (NT0*512)       // 8192 B
#define CHB1 (NT1*512)       // 8192 B
#define CHB2 (NT2*512)       // 4096 B
#define OFF0 0u
#define OFF1 (CH0*CHB0)                  // 819200
#define OFF2 (OFF1 + CH1*CHB1)           // 2129920
#define WPRE_BYTES (OFF2 + CH2*CHB2)     // 2785280

__device__ __align__(16) uint8_t g_wpre[WPRE_BYTES];

// ---------------- helpers ----------------
__device__ __forceinline__ uint32_t packb(float lo, float hi) {
    // d<31:16> = cvt(first src), d<15:0> = cvt(second src)
    uint32_t r;
    asm("cvt.rn.bf16x2.f32 %0, %1, %2;" : "=r"(r) : "f"(hi), "f"(lo));
    return r;
}
__device__ __forceinline__ float bf_round(float v) {
    return __bfloat162float(__float2bfloat16(v));
}
__device__ __forceinline__ void mma_bf16(float* c, const uint32_t* a,
                                         uint32_t b0, uint32_t b1) {
    asm volatile(
        "mma.sync.aligned.m16n8k16.row.col.f32.bf16.bf16.f32 "
        "{%0,%1,%2,%3}, {%4,%5,%6,%7}, {%8,%9}, {%0,%1,%2,%3};"
        : "+f"(c[0]), "+f"(c[1]), "+f"(c[2]), "+f"(c[3])
        : "r"(a[0]), "r"(a[1]), "r"(a[2]), "r"(a[3]), "r"(b0), "r"(b1));
}

// ---------------- prep: split W into bf16 hi/lo B-fragment words ----------------
#define WORDS0 (CH0*NT0*128)
#define WORDS1 (CH1*NT1*128)
#define WORDS2 (CH2*NT2*128)

__global__ void prep_kernel(const float* __restrict__ w0,
                            const float* __restrict__ w1,
                            const float* __restrict__ w2)
{
    int i = blockIdx.x * blockDim.x + threadIdx.x;
    if (i >= WORDS0 + WORDS1 + WORDS2) return;
    const float* src; int NT, ld, rowBase, li; uint32_t off, chb;
    if (i < WORDS0)               { src=w0; NT=NT0; ld=1600; rowBase=0;  off=OFF0; chb=CHB0; li=i; }
    else if (i < WORDS0+WORDS1)   { src=w1; NT=NT1; ld=2560; rowBase=0;  off=OFF1; chb=CHB1; li=i-WORDS0; }
    else                          { src=w2; NT=NT2; ld=2560; rowBase=64; off=OFF2; chb=CHB2; li=i-WORDS0-WORDS1; }

    int perChunk = NT * 128;                 // words per chunk
    int c   = li / perChunk;
    int r   = li - c * perChunk;
    int nt  = r >> 7;                        // / 128
    int r2  = r & 127;
    int s   = r2 >> 6;                       // 0=hi, 1=lo
    int fi  = r2 & 63;
    int lane = fi >> 1;
    int wsel = fi & 1;                       // b0 (k+0..1) or b1 (k+8..9)

    int o = nt * 8 + (lane >> 2);
    int k = c * 16 + (lane & 3) * 2 + wsel * 8;
    float a = __ldg(src + (size_t)(rowBase + o) * ld + k);
    float b = __ldg(src + (size_t)(rowBase + o) * ld + k + 1);
    if (s) { a = a - bf_round(a); b = b - bf_round(b); }
    uint32_t w = packb(a, b);                // low half = k element

    *(uint32_t*)(g_wpre + off + (size_t)c * chb
                 + nt * 512 + s * 256 + lane * 8 + wsel * 4) = w;
}

// ---------------- one CIN layer: K-streamed bf16x3 mma.sync GEMM ----------------
template<int NT>
__device__ __forceinline__ void run_layer(
    int nch, const uint8_t* __restrict__ wpre,
    const float* __restrict__ Pp, const float* __restrict__ Xs,
    uint8_t* __restrict__ wb0, uint8_t* __restrict__ wb1,
    float (&acc)[NT][4], int tid, int lane, int q, int tl)
{
    constexpr int CHB = NT * 512;

    #pragma unroll
    for (int nt = 0; nt < NT; ++nt)
        #pragma unroll
        for (int j = 0; j < 4; ++j) acc[nt][j] = 0.0f;

    __syncthreads();   // previous layer's buffer reads / P writes complete

    // prologue: stage chunk 0 into buf0
    {
        const uint4* s = (const uint4*)wpre;
        uint4* d = (uint4*)wb0;
        #pragma unroll 1
        for (int i = tid; i < CHB / 16; i += THREADS) d[i] = s[i];
    }

    #pragma unroll 1
    for (int c = 0; c < nch; ++c) {
        __syncthreads();                       // chunk c staged; buf (c+1)&1 free
        if (c + 1 < nch) {
            const uint4* s = (const uint4*)(wpre + (size_t)(c + 1) * CHB);
            uint4* d = (uint4*)(((c + 1) & 1) ? wb1 : wb0);
            #pragma unroll 1
            for (int i = tid; i < CHB / 16; i += THREADS) d[i] = s[i];
        }
        const uint8_t* __restrict__ wb = (c & 1) ? wb1 : wb0;

        // ---- build A fragments (hi & lo) for this thread's 2 t-rows ----
        const int k0 = c * 16 + q * 2;
        float zl[4], zh[4];
        #pragma unroll
        for (int e = 0; e < 4; ++e) {
            int k = k0 + (e & 1) + (e >> 1) * 8;   // {k0, k0+1, k0+8, k0+9}
            int h = k / 40;
            int m = k - h * 40;
            float pl = Pp[h * LDP + tl];
            float ph = Pp[h * LDP + tl + 8];
            float xl = Xs[m * LDP + tl];
            float xh = Xs[m * LDP + tl + 8];
            zl[e] = pl * xl;
            zh[e] = ph * xh;
        }
        uint32_t ahi[4], alo[4];
        ahi[0] = packb(zl[0], zl[1]);
        ahi[1] = packb(zh[0], zh[1]);
        ahi[2] = packb(zl[2], zl[3]);
        ahi[3] = packb(zh[2], zh[3]);
        alo[0] = packb(zl[0] - bf_round(zl[0]), zl[1] - bf_round(zl[1]));
        alo[1] = packb(zh[0] - bf_round(zh[0]), zh[1] - bf_round(zh[1]));
        alo[2] = packb(zl[2] - bf_round(zl[2]), zl[3] - bf_round(zl[3]));
        alo[3] = packb(zh[2] - bf_round(zh[2]), zh[3] - bf_round(zh[3]));

        // ---- 3 MMAs per n-tile: hi*hi + lo*hi + hi*lo ----
        #pragma unroll
        for (int nt = 0; nt < NT; ++nt) {
            const uint2 bh = *(const uint2*)(wb + nt * 512 + lane * 8);
            const uint2 bl = *(const uint2*)(wb + nt * 512 + 256 + lane * 8);
            mma_bf16(acc[nt], ahi, bh.x, bh.y);
            mma_bf16(acc[nt], alo, bh.x, bh.y);
            mma_bf16(acc[nt], ahi, bl.x, bl.y);
        }
    }
    __syncthreads();   // all warps done reading smem before epilogue overwrites
}

// ---------------- main kernel ----------------
__global__ void __launch_bounds__(THREADS, 1)
cin_mma_kernel(const float* __restrict__ x,
               const float* __restrict__ b0, const float* __restrict__ b1,
               const float* __restrict__ b2, const float* __restrict__ wl,
               float* __restrict__ out)
{
    extern __shared__ uint8_t smraw[];
    float* Xs = (float*)(smraw + SM_XS);
    float* Ps = (float*)(smraw + SM_PS);
    uint8_t* wb0 = smraw + SM_W0;
    uint8_t* wb1 = smraw + SM_W1;

    const int tid  = threadIdx.x;
    const int warp = tid >> 5;
    const int lane = tid & 31;
    const int q    = lane & 3;        // o-pair / k-pair selector
    const int rr   = lane >> 2;       // row-in-fragment
    const int tl   = warp * 16 + rr;  // this thread's low t-row (high = +8)
    const int bbase = blockIdx.x * 16;

    // X tile: Xs[m][t], t = 16*local_batch + d
    #pragma unroll 1
    for (int i = tid; i < 40 * 256; i += THREADS) {
        int m = i >> 8, t = i & 255;
        Xs[m * LDP + t] = __ldg(x + (size_t)(bbase + (t >> 4)) * 640 + m * 16 + (t & 15));
    }

    float pl = 0.0f, ph = 0.0f;       // direct-feature partials for t=tl, t=tl+8

    // ================= Layer 0: K=1600, P = X =================
    {
        float acc[NT0][4];
        run_layer<NT0>(CH0, g_wpre + OFF0, Xs, Xs, wb0, wb1, acc, tid, lane, q, tl);
        #pragma unroll
        for (int nt = 0; nt < NT0; ++nt) {
            int o = nt * 8 + q * 2;
            float bv0 = __ldg(b0 + o), bv1 = __ldg(b0 + o + 1);
            float v0 = fmaxf(acc[nt][0] + bv0, 0.0f);
            float v1 = fmaxf(acc[nt][1] + bv1, 0.0f);
            float v2 = fmaxf(acc[nt][2] + bv0, 0.0f);
            float v3 = fmaxf(acc[nt][3] + bv1, 0.0f);
            if (nt < 8) {
                Ps[o * LDP + tl]           = v0;
                Ps[(o + 1) * LDP + tl]     = v1;
                Ps[o * LDP + tl + 8]       = v2;
                Ps[(o + 1) * LDP + tl + 8] = v3;
            } else {
                float w0v = __ldg(wl + o - 64), w1v = __ldg(wl + o - 63);
                pl += w0v * v0 + w1v * v1;
                ph += w0v * v2 + w1v * v3;
            }
        }
    }
    // ================= Layer 1: K=2560, P = Ps =================
    {
        float acc[NT1][4];
        run_layer<NT1>(CH1, g_wpre + OFF1, Ps, Xs, wb0, wb1, acc, tid, lane, q, tl);
        #pragma unroll
        for (int nt = 0; nt < NT1; ++nt) {
            int o = nt * 8 + q * 2;
            float bv0 = __ldg(b1 + o), bv1 = __ldg(b1 + o + 1);
            float v0 = fmaxf(acc[nt][0] + bv0, 0.0f);
            float v1 = fmaxf(acc[nt][1] + bv1, 0.0f);
            float v2 = fmaxf(acc[nt][2] + bv0, 0.0f);
            float v3 = fmaxf(acc[nt][3] + bv1, 0.0f);
            if (nt < 8) {
                Ps[o * LDP + tl]           = v0;
                Ps[(o + 1) * LDP + tl]     = v1;
                Ps[o * LDP + tl + 8]       = v2;
                Ps[(o + 1) * LDP + tl + 8] = v3;
            } else {
                float w0v = __ldg(wl + o), w1v = __ldg(wl + o + 1);  // 64 + (o-64)
                pl += w0v * v0 + w1v * v1;
                ph += w0v * v2 + w1v * v3;
            }
        }
    }
    // ========= Layer 2: K=2560, direct half only (N=64) =========
    {
        float acc[NT2][4];
        run_layer<NT2>(CH2, g_wpre + OFF2, Ps, Xs, wb0, wb1, acc, tid, lane, q, tl);
        #pragma unroll
        for (int nt = 0; nt < NT2; ++nt) {
            int o = nt * 8 + q * 2;                  // channel-in-half 0..63
            float bv0 = __ldg(b2 + 64 + o), bv1 = __ldg(b2 + 65 + o);
            float v0 = fmaxf(acc[nt][0] + bv0, 0.0f);
            float v1 = fmaxf(acc[nt][1] + bv1, 0.0f);
            float v2 = fmaxf(acc[nt][2] + bv0, 0.0f);
            float v3 = fmaxf(acc[nt][3] + bv1, 0.0f);
            float w0v = __ldg(wl + 128 + o), w1v = __ldg(wl + 129 + o);
            pl += w0v * v0 + w1v * v1;
            ph += w0v * v2 + w1v * v3;
        }
    }

    // ---- per-batch reduction: warp == batch, sum over its 16 t's ----
    float p = pl + ph;
    #pragma unroll
    for (int off = 16; off >= 1; off >>= 1)
        p += __shfl_xor_sync(0xffffffffu, p, off);
    if (lane == 0) out[bbase + warp] = p;
}

extern "C" void kernel_launch(void* const* d_in, const int* in_sizes, int n_in,
                              void* d_out, int out_size)
{
    const float* x  = (const float*)d_in[0];
    const float* w0 = (const float*)d_in[1];
    const float* b0 = (const float*)d_in[2];
    const float* w1 = (const float*)d_in[3];
    const float* b1 = (const float*)d_in[4];
    const float* w2 = (const float*)d_in[5];
    const float* b2 = (const float*)d_in[6];
    const float* wl = (const float*)d_in[7];
    float* out = (float*)d_out;

    int prepN = WORDS0 + WORDS1 + WORDS2;
    prep_kernel<<<(prepN + 255) / 256, 256>>>(w0, w1, w2);

    cudaFuncSetAttribute(cin_mma_kernel,
                         cudaFuncAttributeMaxDynamicSharedMemorySize, SMEM_BYTES);
    cin_mma_kernel<<<128, THREADS, SMEM_BYTES>>>(x, b0, b1, b2, wl, out);
}